// round 9
// baseline (speedup 1.0000x reference)
#include <cuda_runtime.h>
#include <cuda_bf16.h>
#include <math.h>
#include <stdint.h>

#define BATCH   4
#define SEQ     2048
#define DIM     768
#define HEADS   12
#define HEAD_D  64
#define ATT_SCALE 0.125f   // 1/sqrt(64)
#define RS      (3 * DIM)

// ---------------- scratch (static device globals; no allocation) ----------------
__device__ float g_qkv[(size_t)BATCH * SEQ * 3 * DIM];             // [B,N,3C]
__device__ float g_att[(size_t)BATCH * SEQ * DIM];                 // [B,N,C]
__device__ float g_z  [(size_t)BATCH * HEADS * SEQ];               // Z1 per row
__device__ __nv_bfloat16 g_p[(size_t)BATCH * HEADS * SEQ * SEQ];   // e = exp(s), bf16

// ================================ helpers =======================================
static __device__ __forceinline__ uint32_t f2tf(float f) {
    uint32_t u;
    asm("cvt.rna.tf32.f32 %0, %1;" : "=r"(u) : "f"(f));
    return u;
}

// pack (lo, hi) floats -> bf16x2
static __device__ __forceinline__ uint32_t bf2(float lo, float hi) {
    uint32_t r;
    asm("cvt.rn.bf16x2.f32 %0, %1, %2;" : "=r"(r) : "f"(hi), "f"(lo));
    return r;
}

static __device__ __forceinline__ void mma8(float* c, const uint32_t* a, const uint32_t* b) {
    asm volatile(
        "mma.sync.aligned.m16n8k8.row.col.f32.tf32.tf32.f32 "
        "{%0,%1,%2,%3},{%4,%5,%6,%7},{%8,%9},{%0,%1,%2,%3};"
        : "+f"(c[0]), "+f"(c[1]), "+f"(c[2]), "+f"(c[3])
        : "r"(a[0]), "r"(a[1]), "r"(a[2]), "r"(a[3]), "r"(b[0]), "r"(b[1]));
}

static __device__ __forceinline__ void mma16(float* c, const uint32_t* a, const uint32_t* b) {
    asm volatile(
        "mma.sync.aligned.m16n8k16.row.col.f32.bf16.bf16.f32 "
        "{%0,%1,%2,%3},{%4,%5,%6,%7},{%8,%9},{%0,%1,%2,%3};"
        : "+f"(c[0]), "+f"(c[1]), "+f"(c[2]), "+f"(c[3])
        : "r"(a[0]), "r"(a[1]), "r"(a[2]), "r"(a[3]), "r"(b[0]), "r"(b[1]));
}

// FFMA-only expf (no MUFU): exp(x) for |x| < ~80, rel err ~3e-6
static __device__ __forceinline__ float fexp(float x) {
    float yy = x * 1.4426950408889634f;
    float z  = yy + 12582912.f;
    int  n23 = __float_as_int(z) << 23;
    float f  = yy - (z - 12582912.f);
    float t  = f * 0.6931471805599453f;
    float p  = fmaf(t, fmaf(t, fmaf(t, fmaf(t, fmaf(t,
               0.0083333333f, 0.0416666667f), 0.1666666667f), 0.5f), 1.f), 1.f);
    return __int_as_float(__float_as_int(p) + n23);
}

// =================================================================================
// GEMM-NT (tf32 mma.sync, double-buffered smem): C[M,N] = A[M,K]*B[N,K]^T (+bias)
// BM=BN=128, BK=16; 256 thr = 8 warps (2x4); warp tile 64x32.
// =================================================================================
#define TPITCH 20   // 16 + 4 pad (words) -> conflict-free operand fetch (4r+kc)

__global__ void __launch_bounds__(256)
gemm_tc(const float* __restrict__ A, const float* __restrict__ B,
        const float* __restrict__ bias, float* __restrict__ C,
        int M, int N, int K)
{
    __shared__ uint32_t As[2][128 * TPITCH];
    __shared__ uint32_t Bs[2][128 * TPITCH];

    const int tid = threadIdx.x;
    const int gid = (tid & 31) >> 2, t4 = tid & 3;
    const int w = tid >> 5, wr = w >> 2, wc = w & 3;
    const int m0 = blockIdx.y * 128, n0 = blockIdx.x * 128;
    const int lr = tid >> 2, lc = (tid & 3) * 4;

    float acc[4][4][4];
#pragma unroll
    for (int i = 0; i < 4; i++)
#pragma unroll
        for (int j = 0; j < 4; j++)
#pragma unroll
            for (int u = 0; u < 4; u++) acc[i][j][u] = 0.f;

    float4 pa0 = *(const float4*)&A[(size_t)(m0 + lr) * K + lc];
    float4 pa1 = *(const float4*)&A[(size_t)(m0 + lr + 64) * K + lc];
    float4 pb0 = *(const float4*)&B[(size_t)(n0 + lr) * K + lc];
    float4 pb1 = *(const float4*)&B[(size_t)(n0 + lr + 64) * K + lc];
    {
        uint32_t* d0 = &As[0][lr * TPITCH + lc];
        d0[0] = f2tf(pa0.x); d0[1] = f2tf(pa0.y); d0[2] = f2tf(pa0.z); d0[3] = f2tf(pa0.w);
        uint32_t* d1 = &As[0][(lr + 64) * TPITCH + lc];
        d1[0] = f2tf(pa1.x); d1[1] = f2tf(pa1.y); d1[2] = f2tf(pa1.z); d1[3] = f2tf(pa1.w);
        uint32_t* d2 = &Bs[0][lr * TPITCH + lc];
        d2[0] = f2tf(pb0.x); d2[1] = f2tf(pb0.y); d2[2] = f2tf(pb0.z); d2[3] = f2tf(pb0.w);
        uint32_t* d3 = &Bs[0][(lr + 64) * TPITCH + lc];
        d3[0] = f2tf(pb1.x); d3[1] = f2tf(pb1.y); d3[2] = f2tf(pb1.z); d3[3] = f2tf(pb1.w);
    }
    __syncthreads();

    const int nIter = K / 16;
    for (int i = 0; i < nIter; i++) {
        const int cur = i & 1;
        if (i + 1 < nIter) {
            const int kn = (i + 1) * 16;
            pa0 = *(const float4*)&A[(size_t)(m0 + lr) * K + kn + lc];
            pa1 = *(const float4*)&A[(size_t)(m0 + lr + 64) * K + kn + lc];
            pb0 = *(const float4*)&B[(size_t)(n0 + lr) * K + kn + lc];
            pb1 = *(const float4*)&B[(size_t)(n0 + lr + 64) * K + kn + lc];
        }
#pragma unroll
        for (int kk = 0; kk < 2; kk++) {
            const int kc = kk * 8 + t4;
            uint32_t af[4][4], bfr[4][2];
#pragma unroll
            for (int mt = 0; mt < 4; mt++) {
                int r = wr * 64 + mt * 16 + gid;
                af[mt][0] = As[cur][r * TPITCH + kc];
                af[mt][1] = As[cur][(r + 8) * TPITCH + kc];
                af[mt][2] = As[cur][r * TPITCH + kc + 4];
                af[mt][3] = As[cur][(r + 8) * TPITCH + kc + 4];
            }
#pragma unroll
            for (int nt = 0; nt < 4; nt++) {
                int n = wc * 32 + nt * 8 + gid;
                bfr[nt][0] = Bs[cur][n * TPITCH + kc];
                bfr[nt][1] = Bs[cur][n * TPITCH + kc + 4];
            }
#pragma unroll
            for (int mt = 0; mt < 4; mt++)
#pragma unroll
                for (int nt = 0; nt < 4; nt++)
                    mma8(acc[mt][nt], af[mt], bfr[nt]);
        }
        if (i + 1 < nIter) {
            const int nxt = cur ^ 1;
            uint32_t* d0 = &As[nxt][lr * TPITCH + lc];
            d0[0] = f2tf(pa0.x); d0[1] = f2tf(pa0.y); d0[2] = f2tf(pa0.z); d0[3] = f2tf(pa0.w);
            uint32_t* d1 = &As[nxt][(lr + 64) * TPITCH + lc];
            d1[0] = f2tf(pa1.x); d1[1] = f2tf(pa1.y); d1[2] = f2tf(pa1.z); d1[3] = f2tf(pa1.w);
            uint32_t* d2 = &Bs[nxt][lr * TPITCH + lc];
            d2[0] = f2tf(pb0.x); d2[1] = f2tf(pb0.y); d2[2] = f2tf(pb0.z); d2[3] = f2tf(pb0.w);
            uint32_t* d3 = &Bs[nxt][(lr + 64) * TPITCH + lc];
            d3[0] = f2tf(pb1.x); d3[1] = f2tf(pb1.y); d3[2] = f2tf(pb1.z); d3[3] = f2tf(pb1.w);
        }
        __syncthreads();
    }

#pragma unroll
    for (int mt = 0; mt < 4; mt++) {
        int r = m0 + wr * 64 + mt * 16 + gid;
#pragma unroll
        for (int nt = 0; nt < 4; nt++) {
            int col = n0 + wc * 32 + nt * 8 + t4 * 2;
            float b0 = 0.f, b1 = 0.f;
            if (bias) { b0 = bias[col]; b1 = bias[col + 1]; }
            float2 v0 = make_float2(acc[mt][nt][0] + b0, acc[mt][nt][1] + b1);
            float2 v1 = make_float2(acc[mt][nt][2] + b0, acc[mt][nt][3] + b1);
            *(float2*)&C[(size_t)r * N + col]       = v0;
            *(float2*)&C[(size_t)(r + 8) * N + col] = v1;
        }
    }
}

// =================================================================================
// attn1: per (b,h,128 q-rows) CTA. S = Q K^T (bf16 mma), e = exp(s*scale) -> g_p
// (bf16), Z1 per row -> g_z. No max pass (s*scale ~ N(0,1), exp safe).
// 8 warps (2 row-groups x 4 col-groups); warp tile 64x32 over S[128x128] chunks.
// smem pitch 36 words (pairs) -> conflict-free operand fetch (4r+kc).
// =================================================================================
__global__ void __launch_bounds__(256)
attn1_kernel(const float* __restrict__ qkv, uint32_t* __restrict__ P32,
             float* __restrict__ Zout)
{
    __shared__ uint32_t Qs[128 * 36];
    __shared__ uint32_t Ks[128 * 36];
    __shared__ float    Zp[128 * 4];

    const int tid = threadIdx.x;
    const int gid = (tid & 31) >> 2, t4 = tid & 3;
    const int w = tid >> 5, wr = w >> 2, wc = w & 3;
    const int b = blockIdx.z, h = blockIdx.y, n0 = blockIdx.x * 128;
    const int bh = b * HEADS + h;

    const float* Qg = qkv + (size_t)b * SEQ * RS + h * HEAD_D;
    const float* Kg = Qg + DIM;
    uint32_t* Pb = P32 + (size_t)bh * SEQ * 1024;

    // Q tile 128x64 -> bf16 pairs
#pragma unroll
    for (int i = 0; i < 8; i++) {
        int f = tid + 256 * i;
        int r = f >> 4, c4 = (f & 15) * 4;
        float4 v = *(const float4*)&Qg[(size_t)(n0 + r) * RS + c4];
        *(uint2*)&Qs[r * 36 + (c4 >> 1)] = make_uint2(bf2(v.x, v.y), bf2(v.z, v.w));
    }

    float zacc[4][2];
#pragma unroll
    for (int mt = 0; mt < 4; mt++) { zacc[mt][0] = 0.f; zacc[mt][1] = 0.f; }

    for (int c = 0; c < 16; c++) {
        __syncthreads();
#pragma unroll
        for (int i = 0; i < 8; i++) {
            int f = tid + 256 * i;
            int r = f >> 4, c4 = (f & 15) * 4;
            float4 v = *(const float4*)&Kg[(size_t)(c * 128 + r) * RS + c4];
            *(uint2*)&Ks[r * 36 + (c4 >> 1)] = make_uint2(bf2(v.x, v.y), bf2(v.z, v.w));
        }
        __syncthreads();

        float acc[4][4][4];
#pragma unroll
        for (int mt = 0; mt < 4; mt++)
#pragma unroll
            for (int nt = 0; nt < 4; nt++)
#pragma unroll
                for (int u = 0; u < 4; u++) acc[mt][nt][u] = 0.f;

#pragma unroll
        for (int kk = 0; kk < 4; kk++) {
            uint32_t af[4][4], bfr[4][2];
#pragma unroll
            for (int mt = 0; mt < 4; mt++) {
                int r = wr * 64 + mt * 16 + gid;
                af[mt][0] = Qs[r * 36 + kk * 8 + t4];
                af[mt][1] = Qs[(r + 8) * 36 + kk * 8 + t4];
                af[mt][2] = Qs[r * 36 + kk * 8 + t4 + 4];
                af[mt][3] = Qs[(r + 8) * 36 + kk * 8 + t4 + 4];
            }
#pragma unroll
            for (int nt = 0; nt < 4; nt++) {
                int n = wc * 32 + nt * 8 + gid;
                bfr[nt][0] = Ks[n * 36 + kk * 8 + t4];
                bfr[nt][1] = Ks[n * 36 + kk * 8 + t4 + 4];
            }
#pragma unroll
            for (int mt = 0; mt < 4; mt++)
#pragma unroll
                for (int nt = 0; nt < 4; nt++)
                    mma16(acc[mt][nt], af[mt], bfr[nt]);
        }

        // e = exp(s) -> bf16 gmem, Z1 partials
#pragma unroll
        for (int mt = 0; mt < 4; mt++) {
            int r0 = n0 + wr * 64 + mt * 16 + gid;
#pragma unroll
            for (int nt = 0; nt < 4; nt++) {
                int colp = c * 64 + wc * 16 + nt * 4 + t4;
                float e0 = fexp(acc[mt][nt][0] * ATT_SCALE);
                float e1 = fexp(acc[mt][nt][1] * ATT_SCALE);
                float e2 = fexp(acc[mt][nt][2] * ATT_SCALE);
                float e3 = fexp(acc[mt][nt][3] * ATT_SCALE);
                zacc[mt][0] += e0 + e1;
                zacc[mt][1] += e2 + e3;
                Pb[(size_t)r0 * 1024 + colp]       = bf2(e0, e1);
                Pb[(size_t)(r0 + 8) * 1024 + colp] = bf2(e2, e3);
            }
        }
    }

    // Z1 reduce: quad (t4) shuffle, stage per warp-column, final 4-sum (deterministic)
#pragma unroll
    for (int mt = 0; mt < 4; mt++)
#pragma unroll
        for (int hh = 0; hh < 2; hh++) {
            float z = zacc[mt][hh];
            z += __shfl_xor_sync(~0u, z, 1);
            z += __shfl_xor_sync(~0u, z, 2);
            zacc[mt][hh] = z;
        }
    if (t4 == 0) {
#pragma unroll
        for (int mt = 0; mt < 4; mt++)
#pragma unroll
            for (int hh = 0; hh < 2; hh++) {
                int rl = wr * 64 + mt * 16 + gid + 8 * hh;
                Zp[rl * 4 + wc] = zacc[mt][hh];
            }
    }
    __syncthreads();
    if (tid < 128) {
        float z = (Zp[tid * 4] + Zp[tid * 4 + 1]) + (Zp[tid * 4 + 2] + Zp[tid * 4 + 3]);
        Zout[(size_t)bh * SEQ + n0 + tid] = z;
    }
}

// =================================================================================
// attn2: per (b,h,128 q-rows) CTA.  pp = p + p^2/2 + p^3/6  (p = e/Z1), all bf16.
// O = (Sv + PP*V) / Z2,  Z2 = 2048 + sum(pp),  Sv = column sums of V (fp32 exact).
// 8 warps (4 row-groups x 2 col-groups); warp tile 32x32 over O[128x64].
// =================================================================================
#define A2_SMEM ((128 * 68 + 64 * 68) * 4 + (16 * 64 + 128 + 128 + 64) * 4)

__global__ void __launch_bounds__(256)
attn2_kernel(const float* __restrict__ qkv, const uint32_t* __restrict__ P32,
             const float* __restrict__ Zin, float* __restrict__ att)
{
    extern __shared__ uint32_t sm2[];
    uint32_t* Ps  = sm2;                        // [128][68] pp pairs
    uint32_t* Vt  = sm2 + 128 * 68;             // [64 d][68] V pairs (m-pairs)
    float*    SvP = (float*)(sm2 + 128 * 68 + 64 * 68);   // [16][64]
    float*    Zb  = SvP + 16 * 64;              // [128] Z2
    float*    sZ1 = Zb + 128;                   // [128] 1/Z1
    float*    Sv  = sZ1 + 128;                  // [64]

    const int tid = threadIdx.x;
    const int gid = (tid & 31) >> 2, t4 = tid & 3;
    const int w = tid >> 5, wq = w >> 1, wd = w & 1;
    const int b = blockIdx.z, h = blockIdx.y, n0 = blockIdx.x * 128;
    const int bh = b * HEADS + h;

    const float* Vg = qkv + (size_t)b * SEQ * RS + h * HEAD_D + 2 * DIM;
    const uint32_t* Pg = P32 + (size_t)bh * SEQ * 1024 + (size_t)n0 * 1024;

    if (tid < 128) sZ1[tid] = 1.0f / Zin[(size_t)bh * SEQ + n0 + tid];

    float acc[2][4][4];
#pragma unroll
    for (int i = 0; i < 2; i++)
#pragma unroll
        for (int j = 0; j < 4; j++)
#pragma unroll
            for (int u = 0; u < 4; u++) acc[i][j][u] = 0.f;
    float zacc = 0.f;
    float svacc[4] = {0.f, 0.f, 0.f, 0.f};

    const int d4 = (tid & 15) * 4;       // V-fill column group
    const int rr = tid >> 1, sub = tid & 1;  // pp-fill row / half

    __syncthreads();
    const float inv1 = sZ1[rr];

    for (int c = 0; c < 16; c++) {
        __syncthreads();
        // V chunk -> bf16 pairs (transposed) + fp32 column-sum accumulation
#pragma unroll
        for (int it = 0; it < 4; it++) {
            int mp = (tid >> 4) + 16 * it;
            const float* vp = &Vg[(size_t)(c * 128 + 2 * mp) * RS + d4];
            float4 a = *(const float4*)vp;
            float4 bb = *(const float4*)(vp + RS);
            svacc[0] += a.x + bb.x;
            svacc[1] += a.y + bb.y;
            svacc[2] += a.z + bb.z;
            svacc[3] += a.w + bb.w;
            Vt[(d4 + 0) * 68 + mp] = bf2(a.x, bb.x);
            Vt[(d4 + 1) * 68 + mp] = bf2(a.y, bb.y);
            Vt[(d4 + 2) * 68 + mp] = bf2(a.z, bb.z);
            Vt[(d4 + 3) * 68 + mp] = bf2(a.w, bb.w);
        }
        // e -> pp = p + p^2/2 + p^3/6, accumulate Z2, store bf16 pairs
#pragma unroll
        for (int it = 0; it < 8; it++) {
            int c16 = sub * 8 + it;
            uint4 ev = *(const uint4*)&Pg[(size_t)rr * 1024 + c * 64 + c16 * 4];
            uint32_t ws[4] = {ev.x, ev.y, ev.z, ev.w};
            uint32_t* d = &Ps[rr * 68 + c16 * 4];
#pragma unroll
            for (int u = 0; u < 4; u++) {
                float p0 = __uint_as_float(ws[u] << 16) * inv1;
                float p1 = __uint_as_float(ws[u] & 0xffff0000u) * inv1;
                float t0 = fmaf(p0, 0.16666667f, 0.5f);
                float t1 = fmaf(p1, 0.16666667f, 0.5f);
                float pp0 = p0 * fmaf(p0, t0, 1.0f);
                float pp1 = p1 * fmaf(p1, t1, 1.0f);
                zacc += pp0 + pp1;
                d[u] = bf2(pp0, pp1);
            }
        }
        __syncthreads();
        // D += PP * V
#pragma unroll
        for (int kk = 0; kk < 8; kk++) {
            uint32_t af[2][4], bfr[4][2];
#pragma unroll
            for (int mt = 0; mt < 2; mt++) {
                int r = wq * 32 + mt * 16 + gid;
                af[mt][0] = Ps[r * 68 + kk * 8 + t4];
                af[mt][1] = Ps[(r + 8) * 68 + kk * 8 + t4];
                af[mt][2] = Ps[r * 68 + kk * 8 + t4 + 4];
                af[mt][3] = Ps[(r + 8) * 68 + kk * 8 + t4 + 4];
            }
#pragma unroll
            for (int nt = 0; nt < 4; nt++) {
                int n = wd * 32 + nt * 8 + gid;
                bfr[nt][0] = Vt[n * 68 + kk * 8 + t4];
                bfr[nt][1] = Vt[n * 68 + kk * 8 + t4 + 4];
            }
#pragma unroll
            for (int mt = 0; mt < 2; mt++)
#pragma unroll
                for (int nt = 0; nt < 4; nt++)
                    mma16(acc[mt][nt], af[mt], bfr[nt]);
        }
    }

    // Z2 per row (pairs of threads share row rr)
    {
        float z = zacc + __shfl_xor_sync(~0u, zacc, 1);
        if (sub == 0) Zb[rr] = 2048.f + z;
    }
    // Sv reduce (deterministic fixed order)
#pragma unroll
    for (int u = 0; u < 4; u++) SvP[(tid >> 4) * 64 + d4 + u] = svacc[u];
    __syncthreads();
    if (tid < 64) {
        float s = 0.f;
#pragma unroll
        for (int g = 0; g < 16; g++) s += SvP[g * 64 + tid];
        Sv[tid] = s;
    }
    __syncthreads();

    // epilogue: O = (Sv + D) / Z2
#pragma unroll
    for (int mt = 0; mt < 2; mt++) {
        int r0 = wq * 32 + mt * 16 + gid;
        float i0 = 1.0f / Zb[r0];
        float i1 = 1.0f / Zb[r0 + 8];
#pragma unroll
        for (int nt = 0; nt < 4; nt++) {
            int cd = wd * 32 + nt * 8 + 2 * t4;
            float s0 = Sv[cd], s1 = Sv[cd + 1];
            float2 v0 = make_float2((acc[mt][nt][0] + s0) * i0, (acc[mt][nt][1] + s1) * i0);
            float2 v1 = make_float2((acc[mt][nt][2] + s0) * i1, (acc[mt][nt][3] + s1) * i1);
            *(float2*)&att[(size_t)(b * SEQ + n0 + r0) * DIM + h * HEAD_D + cd]     = v0;
            *(float2*)&att[(size_t)(b * SEQ + n0 + r0 + 8) * DIM + h * HEAD_D + cd] = v1;
        }
    }
}

// =================================================================================
// launch
// =================================================================================
extern "C" void kernel_launch(void* const* d_in, const int* in_sizes, int n_in,
                              void* d_out, int out_size)
{
    const float* x      = (const float*)d_in[0];   // [4,2048,768]
    const float* w_qkv  = (const float*)d_in[1];   // [2304,768]
    const float* w_proj = (const float*)d_in[2];   // [768,768]
    const float* b_proj = (const float*)d_in[3];   // [768]
    float* out = (float*)d_out;                    // [4,2048,768]

    void* p0; cudaGetSymbolAddress(&p0, g_qkv);
    void* p1; cudaGetSymbolAddress(&p1, g_att);
    void* p2; cudaGetSymbolAddress(&p2, g_z);
    void* p3; cudaGetSymbolAddress(&p3, g_p);
    float* qkv = (float*)p0;
    float* att = (float*)p1;
    float* zbuf = (float*)p2;
    uint32_t* pbuf = (uint32_t*)p3;

    cudaFuncSetAttribute(attn2_kernel, cudaFuncAttributeMaxDynamicSharedMemorySize, A2_SMEM);

    const int M = BATCH * SEQ;   // 8192

    // 1) qkv = x @ w_qkv^T
    {
        dim3 grid((3 * DIM) / 128, M / 128);
        gemm_tc<<<grid, 256>>>(x, w_qkv, nullptr, qkv, M, 3 * DIM, DIM);
    }
    // 2a) S=QK^T (bf16), e=exp(s), Z1
    {
        dim3 grid(SEQ / 128, HEADS, BATCH);
        attn1_kernel<<<grid, 256>>>(qkv, pbuf, zbuf);
    }
    // 2b) pp=p+p^2/2+p^3/6, O=(Sv + PP V)/Z2
    {
        dim3 grid(SEQ / 128, HEADS, BATCH);
        attn2_kernel<<<grid, 256, A2_SMEM>>>(qkv, pbuf, zbuf, att);
    }
    // 3) out = att @ w_proj^T + b
    {
        dim3 grid(DIM / 128, M / 128);
        gemm_tc<<<grid, 256>>>(att, w_proj, b_proj, out, M, DIM, DIM);
    }
}

// round 10
// speedup vs baseline: 1.0009x; 1.0009x over previous
#include <cuda_runtime.h>
#include <cuda_bf16.h>
#include <math.h>
#include <stdint.h>

#define BATCH   4
#define SEQ     2048
#define DIM     768
#define HEADS   12
#define HEAD_D  64
#define ATT_SCALE 0.125f   // 1/sqrt(64)
#define RS      (3 * DIM)

// ---------------- scratch (static device globals; no allocation) ----------------
__device__ float g_qkv[(size_t)BATCH * SEQ * 3 * DIM];             // [B,N,3C]
__device__ float g_att[(size_t)BATCH * SEQ * DIM];                 // [B,N,C]
__device__ float g_z  [(size_t)BATCH * HEADS * SEQ];               // Z1 per row
__device__ __nv_bfloat16 g_p[(size_t)BATCH * HEADS * SEQ * SEQ];   // e = exp(s), bf16

// ================================ helpers =======================================
static __device__ __forceinline__ uint32_t f2tf(float f) {
    uint32_t u;
    asm("cvt.rna.tf32.f32 %0, %1;" : "=r"(u) : "f"(f));
    return u;
}

// pack (lo, hi) floats -> bf16x2
static __device__ __forceinline__ uint32_t bf2(float lo, float hi) {
    uint32_t r;
    asm("cvt.rn.bf16x2.f32 %0, %1, %2;" : "=r"(r) : "f"(hi), "f"(lo));
    return r;
}

static __device__ __forceinline__ void mma8(float* c, const uint32_t* a, const uint32_t* b) {
    asm volatile(
        "mma.sync.aligned.m16n8k8.row.col.f32.tf32.tf32.f32 "
        "{%0,%1,%2,%3},{%4,%5,%6,%7},{%8,%9},{%0,%1,%2,%3};"
        : "+f"(c[0]), "+f"(c[1]), "+f"(c[2]), "+f"(c[3])
        : "r"(a[0]), "r"(a[1]), "r"(a[2]), "r"(a[3]), "r"(b[0]), "r"(b[1]));
}

static __device__ __forceinline__ void mma16(float* c, const uint32_t* a, const uint32_t* b) {
    asm volatile(
        "mma.sync.aligned.m16n8k16.row.col.f32.bf16.bf16.f32 "
        "{%0,%1,%2,%3},{%4,%5,%6,%7},{%8,%9},{%0,%1,%2,%3};"
        : "+f"(c[0]), "+f"(c[1]), "+f"(c[2]), "+f"(c[3])
        : "r"(a[0]), "r"(a[1]), "r"(a[2]), "r"(a[3]), "r"(b[0]), "r"(b[1]));
}

// FFMA-only expf (no MUFU): exp(x) for |x| < ~80, rel err ~3e-6
static __device__ __forceinline__ float fexp(float x) {
    float yy = x * 1.4426950408889634f;
    float z  = yy + 12582912.f;
    int  n23 = __float_as_int(z) << 23;
    float f  = yy - (z - 12582912.f);
    float t  = f * 0.6931471805599453f;
    float p  = fmaf(t, fmaf(t, fmaf(t, fmaf(t, fmaf(t,
               0.0083333333f, 0.0416666667f), 0.1666666667f), 0.5f), 1.f), 1.f);
    return __int_as_float(__float_as_int(p) + n23);
}

// =================================================================================
// GEMM-NT (tf32 mma.sync, double-buffered smem): C[M,N] = A[M,K]*B[N,K]^T (+bias)
// BM=BN=128, BK=16; 256 thr = 8 warps (2x4); warp tile 64x32.
// =================================================================================
#define TPITCH 20   // 16 + 4 pad (words) -> conflict-free operand fetch (4r+kc)

__global__ void __launch_bounds__(256)
gemm_tc(const float* __restrict__ A, const float* __restrict__ B,
        const float* __restrict__ bias, float* __restrict__ C,
        int M, int N, int K)
{
    __shared__ uint32_t As[2][128 * TPITCH];
    __shared__ uint32_t Bs[2][128 * TPITCH];

    const int tid = threadIdx.x;
    const int gid = (tid & 31) >> 2, t4 = tid & 3;
    const int w = tid >> 5, wr = w >> 2, wc = w & 3;
    const int m0 = blockIdx.y * 128, n0 = blockIdx.x * 128;
    const int lr = tid >> 2, lc = (tid & 3) * 4;

    float acc[4][4][4];
#pragma unroll
    for (int i = 0; i < 4; i++)
#pragma unroll
        for (int j = 0; j < 4; j++)
#pragma unroll
            for (int u = 0; u < 4; u++) acc[i][j][u] = 0.f;

    float4 pa0 = *(const float4*)&A[(size_t)(m0 + lr) * K + lc];
    float4 pa1 = *(const float4*)&A[(size_t)(m0 + lr + 64) * K + lc];
    float4 pb0 = *(const float4*)&B[(size_t)(n0 + lr) * K + lc];
    float4 pb1 = *(const float4*)&B[(size_t)(n0 + lr + 64) * K + lc];
    {
        uint32_t* d0 = &As[0][lr * TPITCH + lc];
        d0[0] = f2tf(pa0.x); d0[1] = f2tf(pa0.y); d0[2] = f2tf(pa0.z); d0[3] = f2tf(pa0.w);
        uint32_t* d1 = &As[0][(lr + 64) * TPITCH + lc];
        d1[0] = f2tf(pa1.x); d1[1] = f2tf(pa1.y); d1[2] = f2tf(pa1.z); d1[3] = f2tf(pa1.w);
        uint32_t* d2 = &Bs[0][lr * TPITCH + lc];
        d2[0] = f2tf(pb0.x); d2[1] = f2tf(pb0.y); d2[2] = f2tf(pb0.z); d2[3] = f2tf(pb0.w);
        uint32_t* d3 = &Bs[0][(lr + 64) * TPITCH + lc];
        d3[0] = f2tf(pb1.x); d3[1] = f2tf(pb1.y); d3[2] = f2tf(pb1.z); d3[3] = f2tf(pb1.w);
    }
    __syncthreads();

    const int nIter = K / 16;
    for (int i = 0; i < nIter; i++) {
        const int cur = i & 1;
        if (i + 1 < nIter) {
            const int kn = (i + 1) * 16;
            pa0 = *(const float4*)&A[(size_t)(m0 + lr) * K + kn + lc];
            pa1 = *(const float4*)&A[(size_t)(m0 + lr + 64) * K + kn + lc];
            pb0 = *(const float4*)&B[(size_t)(n0 + lr) * K + kn + lc];
            pb1 = *(const float4*)&B[(size_t)(n0 + lr + 64) * K + kn + lc];
        }
#pragma unroll
        for (int kk = 0; kk < 2; kk++) {
            const int kc = kk * 8 + t4;
            uint32_t af[4][4], bfr[4][2];
#pragma unroll
            for (int mt = 0; mt < 4; mt++) {
                int r = wr * 64 + mt * 16 + gid;
                af[mt][0] = As[cur][r * TPITCH + kc];
                af[mt][1] = As[cur][(r + 8) * TPITCH + kc];
                af[mt][2] = As[cur][r * TPITCH + kc + 4];
                af[mt][3] = As[cur][(r + 8) * TPITCH + kc + 4];
            }
#pragma unroll
            for (int nt = 0; nt < 4; nt++) {
                int n = wc * 32 + nt * 8 + gid;
                bfr[nt][0] = Bs[cur][n * TPITCH + kc];
                bfr[nt][1] = Bs[cur][n * TPITCH + kc + 4];
            }
#pragma unroll
            for (int mt = 0; mt < 4; mt++)
#pragma unroll
                for (int nt = 0; nt < 4; nt++)
                    mma8(acc[mt][nt], af[mt], bfr[nt]);
        }
        if (i + 1 < nIter) {
            const int nxt = cur ^ 1;
            uint32_t* d0 = &As[nxt][lr * TPITCH + lc];
            d0[0] = f2tf(pa0.x); d0[1] = f2tf(pa0.y); d0[2] = f2tf(pa0.z); d0[3] = f2tf(pa0.w);
            uint32_t* d1 = &As[nxt][(lr + 64) * TPITCH + lc];
            d1[0] = f2tf(pa1.x); d1[1] = f2tf(pa1.y); d1[2] = f2tf(pa1.z); d1[3] = f2tf(pa1.w);
            uint32_t* d2 = &Bs[nxt][lr * TPITCH + lc];
            d2[0] = f2tf(pb0.x); d2[1] = f2tf(pb0.y); d2[2] = f2tf(pb0.z); d2[3] = f2tf(pb0.w);
            uint32_t* d3 = &Bs[nxt][(lr + 64) * TPITCH + lc];
            d3[0] = f2tf(pb1.x); d3[1] = f2tf(pb1.y); d3[2] = f2tf(pb1.z); d3[3] = f2tf(pb1.w);
        }
        __syncthreads();
    }

#pragma unroll
    for (int mt = 0; mt < 4; mt++) {
        int r = m0 + wr * 64 + mt * 16 + gid;
#pragma unroll
        for (int nt = 0; nt < 4; nt++) {
            int col = n0 + wc * 32 + nt * 8 + t4 * 2;
            float b0 = 0.f, b1 = 0.f;
            if (bias) { b0 = bias[col]; b1 = bias[col + 1]; }
            float2 v0 = make_float2(acc[mt][nt][0] + b0, acc[mt][nt][1] + b1);
            float2 v1 = make_float2(acc[mt][nt][2] + b0, acc[mt][nt][3] + b1);
            *(float2*)&C[(size_t)r * N + col]       = v0;
            *(float2*)&C[(size_t)(r + 8) * N + col] = v1;
        }
    }
}

// =================================================================================
// attn1: per (b,h,128 q-rows) CTA. S = Q K^T (bf16 mma), e = exp(s*scale) -> g_p
// (bf16), Z1 per row -> g_z. No max pass (s*scale ~ N(0,1), exp safe).
// 8 warps (2 row-groups x 4 col-groups); warp tile 64x32 over S[128x128] chunks.
// smem pitch 36 words (pairs) -> conflict-free operand fetch (4r+kc).
// =================================================================================
__global__ void __launch_bounds__(256)
attn1_kernel(const float* __restrict__ qkv, uint32_t* __restrict__ P32,
             float* __restrict__ Zout)
{
    __shared__ uint32_t Qs[128 * 36];
    __shared__ uint32_t Ks[128 * 36];
    __shared__ float    Zp[128 * 4];

    const int tid = threadIdx.x;
    const int gid = (tid & 31) >> 2, t4 = tid & 3;
    const int w = tid >> 5, wr = w >> 2, wc = w & 3;
    const int b = blockIdx.z, h = blockIdx.y, n0 = blockIdx.x * 128;
    const int bh = b * HEADS + h;

    const float* Qg = qkv + (size_t)b * SEQ * RS + h * HEAD_D;
    const float* Kg = Qg + DIM;
    uint32_t* Pb = P32 + (size_t)bh * SEQ * 1024;

    // Q tile 128x64 -> bf16 pairs
#pragma unroll
    for (int i = 0; i < 8; i++) {
        int f = tid + 256 * i;
        int r = f >> 4, c4 = (f & 15) * 4;
        float4 v = *(const float4*)&Qg[(size_t)(n0 + r) * RS + c4];
        *(uint2*)&Qs[r * 36 + (c4 >> 1)] = make_uint2(bf2(v.x, v.y), bf2(v.z, v.w));
    }

    float zacc[4][2];
#pragma unroll
    for (int mt = 0; mt < 4; mt++) { zacc[mt][0] = 0.f; zacc[mt][1] = 0.f; }

    for (int c = 0; c < 16; c++) {
        __syncthreads();
#pragma unroll
        for (int i = 0; i < 8; i++) {
            int f = tid + 256 * i;
            int r = f >> 4, c4 = (f & 15) * 4;
            float4 v = *(const float4*)&Kg[(size_t)(c * 128 + r) * RS + c4];
            *(uint2*)&Ks[r * 36 + (c4 >> 1)] = make_uint2(bf2(v.x, v.y), bf2(v.z, v.w));
        }
        __syncthreads();

        float acc[4][4][4];
#pragma unroll
        for (int mt = 0; mt < 4; mt++)
#pragma unroll
            for (int nt = 0; nt < 4; nt++)
#pragma unroll
                for (int u = 0; u < 4; u++) acc[mt][nt][u] = 0.f;

#pragma unroll
        for (int kk = 0; kk < 4; kk++) {
            uint32_t af[4][4], bfr[4][2];
#pragma unroll
            for (int mt = 0; mt < 4; mt++) {
                int r = wr * 64 + mt * 16 + gid;
                af[mt][0] = Qs[r * 36 + kk * 8 + t4];
                af[mt][1] = Qs[(r + 8) * 36 + kk * 8 + t4];
                af[mt][2] = Qs[r * 36 + kk * 8 + t4 + 4];
                af[mt][3] = Qs[(r + 8) * 36 + kk * 8 + t4 + 4];
            }
#pragma unroll
            for (int nt = 0; nt < 4; nt++) {
                int n = wc * 32 + nt * 8 + gid;
                bfr[nt][0] = Ks[n * 36 + kk * 8 + t4];
                bfr[nt][1] = Ks[n * 36 + kk * 8 + t4 + 4];
            }
#pragma unroll
            for (int mt = 0; mt < 4; mt++)
#pragma unroll
                for (int nt = 0; nt < 4; nt++)
                    mma16(acc[mt][nt], af[mt], bfr[nt]);
        }

        // e = exp(s) -> bf16 gmem, Z1 partials
#pragma unroll
        for (int mt = 0; mt < 4; mt++) {
            int r0 = n0 + wr * 64 + mt * 16 + gid;
#pragma unroll
            for (int nt = 0; nt < 4; nt++) {
                int colp = c * 64 + wc * 16 + nt * 4 + t4;
                float e0 = fexp(acc[mt][nt][0] * ATT_SCALE);
                float e1 = fexp(acc[mt][nt][1] * ATT_SCALE);
                float e2 = fexp(acc[mt][nt][2] * ATT_SCALE);
                float e3 = fexp(acc[mt][nt][3] * ATT_SCALE);
                zacc[mt][0] += e0 + e1;
                zacc[mt][1] += e2 + e3;
                Pb[(size_t)r0 * 1024 + colp]       = bf2(e0, e1);
                Pb[(size_t)(r0 + 8) * 1024 + colp] = bf2(e2, e3);
            }
        }
    }

    // Z1 reduce: quad (t4) shuffle, stage per warp-column, final 4-sum (deterministic)
#pragma unroll
    for (int mt = 0; mt < 4; mt++)
#pragma unroll
        for (int hh = 0; hh < 2; hh++) {
            float z = zacc[mt][hh];
            z += __shfl_xor_sync(~0u, z, 1);
            z += __shfl_xor_sync(~0u, z, 2);
            zacc[mt][hh] = z;
        }
    if (t4 == 0) {
#pragma unroll
        for (int mt = 0; mt < 4; mt++)
#pragma unroll
            for (int hh = 0; hh < 2; hh++) {
                int rl = wr * 64 + mt * 16 + gid + 8 * hh;
                Zp[rl * 4 + wc] = zacc[mt][hh];
            }
    }
    __syncthreads();
    if (tid < 128) {
        float z = (Zp[tid * 4] + Zp[tid * 4 + 1]) + (Zp[tid * 4 + 2] + Zp[tid * 4 + 3]);
        Zout[(size_t)bh * SEQ + n0 + tid] = z;
    }
}

// =================================================================================
// attn2: per (b,h,128 q-rows) CTA.  pp = p + p^2/2 + p^3/6  (p = e/Z1), all bf16.
// O = (Sv + PP*V) / Z2,  Z2 = 2048 + sum(pp),  Sv = column sums of V (fp32 exact).
// 8 warps (4 row-groups x 2 col-groups); warp tile 32x32 over O[128x64].
// =================================================================================
#define A2_SMEM ((128 * 68 + 64 * 68) * 4 + (16 * 64 + 128 + 128 + 64) * 4)

__global__ void __launch_bounds__(256)
attn2_kernel(const float* __restrict__ qkv, const uint32_t* __restrict__ P32,
             const float* __restrict__ Zin, float* __restrict__ att)
{
    extern __shared__ uint32_t sm2[];
    uint32_t* Ps  = sm2;                        // [128][68] pp pairs
    uint32_t* Vt  = sm2 + 128 * 68;             // [64 d][68] V pairs (m-pairs)
    float*    SvP = (float*)(sm2 + 128 * 68 + 64 * 68);   // [16][64]
    float*    Zb  = SvP + 16 * 64;              // [128] Z2
    float*    sZ1 = Zb + 128;                   // [128] 1/Z1
    float*    Sv  = sZ1 + 128;                  // [64]

    const int tid = threadIdx.x;
    const int gid = (tid & 31) >> 2, t4 = tid & 3;
    const int w = tid >> 5, wq = w >> 1, wd = w & 1;
    const int b = blockIdx.z, h = blockIdx.y, n0 = blockIdx.x * 128;
    const int bh = b * HEADS + h;

    const float* Vg = qkv + (size_t)b * SEQ * RS + h * HEAD_D + 2 * DIM;
    const uint32_t* Pg = P32 + (size_t)bh * SEQ * 1024 + (size_t)n0 * 1024;

    if (tid < 128) sZ1[tid] = 1.0f / Zin[(size_t)bh * SEQ + n0 + tid];

    float acc[2][4][4];
#pragma unroll
    for (int i = 0; i < 2; i++)
#pragma unroll
        for (int j = 0; j < 4; j++)
#pragma unroll
            for (int u = 0; u < 4; u++) acc[i][j][u] = 0.f;
    float zacc = 0.f;
    float svacc[4] = {0.f, 0.f, 0.f, 0.f};

    const int d4 = (tid & 15) * 4;       // V-fill column group
    const int rr = tid >> 1, sub = tid & 1;  // pp-fill row / half

    __syncthreads();
    const float inv1 = sZ1[rr];

    for (int c = 0; c < 16; c++) {
        __syncthreads();
        // V chunk -> bf16 pairs (transposed) + fp32 column-sum accumulation
#pragma unroll
        for (int it = 0; it < 4; it++) {
            int mp = (tid >> 4) + 16 * it;
            const float* vp = &Vg[(size_t)(c * 128 + 2 * mp) * RS + d4];
            float4 a = *(const float4*)vp;
            float4 bb = *(const float4*)(vp + RS);
            svacc[0] += a.x + bb.x;
            svacc[1] += a.y + bb.y;
            svacc[2] += a.z + bb.z;
            svacc[3] += a.w + bb.w;
            Vt[(d4 + 0) * 68 + mp] = bf2(a.x, bb.x);
            Vt[(d4 + 1) * 68 + mp] = bf2(a.y, bb.y);
            Vt[(d4 + 2) * 68 + mp] = bf2(a.z, bb.z);
            Vt[(d4 + 3) * 68 + mp] = bf2(a.w, bb.w);
        }
        // e -> pp = p + p^2/2 + p^3/6, accumulate Z2, store bf16 pairs
#pragma unroll
        for (int it = 0; it < 8; it++) {
            int c16 = sub * 8 + it;
            uint4 ev = *(const uint4*)&Pg[(size_t)rr * 1024 + c * 64 + c16 * 4];
            uint32_t ws[4] = {ev.x, ev.y, ev.z, ev.w};
            uint32_t* d = &Ps[rr * 68 + c16 * 4];
#pragma unroll
            for (int u = 0; u < 4; u++) {
                float p0 = __uint_as_float(ws[u] << 16) * inv1;
                float p1 = __uint_as_float(ws[u] & 0xffff0000u) * inv1;
                float t0 = fmaf(p0, 0.16666667f, 0.5f);
                float t1 = fmaf(p1, 0.16666667f, 0.5f);
                float pp0 = p0 * fmaf(p0, t0, 1.0f);
                float pp1 = p1 * fmaf(p1, t1, 1.0f);
                zacc += pp0 + pp1;
                d[u] = bf2(pp0, pp1);
            }
        }
        __syncthreads();
        // D += PP * V
#pragma unroll
        for (int kk = 0; kk < 8; kk++) {
            uint32_t af[2][4], bfr[4][2];
#pragma unroll
            for (int mt = 0; mt < 2; mt++) {
                int r = wq * 32 + mt * 16 + gid;
                af[mt][0] = Ps[r * 68 + kk * 8 + t4];
                af[mt][1] = Ps[(r + 8) * 68 + kk * 8 + t4];
                af[mt][2] = Ps[r * 68 + kk * 8 + t4 + 4];
                af[mt][3] = Ps[(r + 8) * 68 + kk * 8 + t4 + 4];
            }
#pragma unroll
            for (int nt = 0; nt < 4; nt++) {
                int n = wd * 32 + nt * 8 + gid;
                bfr[nt][0] = Vt[n * 68 + kk * 8 + t4];
                bfr[nt][1] = Vt[n * 68 + kk * 8 + t4 + 4];
            }
#pragma unroll
            for (int mt = 0; mt < 2; mt++)
#pragma unroll
                for (int nt = 0; nt < 4; nt++)
                    mma16(acc[mt][nt], af[mt], bfr[nt]);
        }
    }

    // Z2 per row (pairs of threads share row rr)
    {
        float z = zacc + __shfl_xor_sync(~0u, zacc, 1);
        if (sub == 0) Zb[rr] = 2048.f + z;
    }
    // Sv reduce (deterministic fixed order)
#pragma unroll
    for (int u = 0; u < 4; u++) SvP[(tid >> 4) * 64 + d4 + u] = svacc[u];
    __syncthreads();
    if (tid < 64) {
        float s = 0.f;
#pragma unroll
        for (int g = 0; g < 16; g++) s += SvP[g * 64 + tid];
        Sv[tid] = s;
    }
    __syncthreads();

    // epilogue: O = (Sv + D) / Z2
#pragma unroll
    for (int mt = 0; mt < 2; mt++) {
        int r0 = wq * 32 + mt * 16 + gid;
        float i0 = 1.0f / Zb[r0];
        float i1 = 1.0f / Zb[r0 + 8];
#pragma unroll
        for (int nt = 0; nt < 4; nt++) {
            int cd = wd * 32 + nt * 8 + 2 * t4;
            float s0 = Sv[cd], s1 = Sv[cd + 1];
            float2 v0 = make_float2((acc[mt][nt][0] + s0) * i0, (acc[mt][nt][1] + s1) * i0);
            float2 v1 = make_float2((acc[mt][nt][2] + s0) * i1, (acc[mt][nt][3] + s1) * i1);
            *(float2*)&att[(size_t)(b * SEQ + n0 + r0) * DIM + h * HEAD_D + cd]     = v0;
            *(float2*)&att[(size_t)(b * SEQ + n0 + r0 + 8) * DIM + h * HEAD_D + cd] = v1;
        }
    }
}

// =================================================================================
// launch
// =================================================================================
extern "C" void kernel_launch(void* const* d_in, const int* in_sizes, int n_in,
                              void* d_out, int out_size)
{
    const float* x      = (const float*)d_in[0];   // [4,2048,768]
    const float* w_qkv  = (const float*)d_in[1];   // [2304,768]
    const float* w_proj = (const float*)d_in[2];   // [768,768]
    const float* b_proj = (const float*)d_in[3];   // [768]
    float* out = (float*)d_out;                    // [4,2048,768]

    void* p0; cudaGetSymbolAddress(&p0, g_qkv);
    void* p1; cudaGetSymbolAddress(&p1, g_att);
    void* p2; cudaGetSymbolAddress(&p2, g_z);
    void* p3; cudaGetSymbolAddress(&p3, g_p);
    float* qkv = (float*)p0;
    float* att = (float*)p1;
    float* zbuf = (float*)p2;
    uint32_t* pbuf = (uint32_t*)p3;

    cudaFuncSetAttribute(attn2_kernel, cudaFuncAttributeMaxDynamicSharedMemorySize, A2_SMEM);

    const int M = BATCH * SEQ;   // 8192

    // 1) qkv = x @ w_qkv^T
    {
        dim3 grid((3 * DIM) / 128, M / 128);
        gemm_tc<<<grid, 256>>>(x, w_qkv, nullptr, qkv, M, 3 * DIM, DIM);
    }
    // 2a) S=QK^T (bf16), e=exp(s), Z1
    {
        dim3 grid(SEQ / 128, HEADS, BATCH);
        attn1_kernel<<<grid, 256>>>(qkv, pbuf, zbuf);
    }
    // 2b) pp=p+p^2/2+p^3/6, O=(Sv + PP V)/Z2
    {
        dim3 grid(SEQ / 128, HEADS, BATCH);
        attn2_kernel<<<grid, 256, A2_SMEM>>>(qkv, pbuf, zbuf, att);
    }
    // 3) out = att @ w_proj^T + b
    {
        dim3 grid(DIM / 128, M / 128);
        gemm_tc<<<grid, 256>>>(att, w_proj, b_proj, out, M, DIM, DIM);
    }
}

// round 11
// speedup vs baseline: 1.0031x; 1.0022x over previous
#include <cuda_runtime.h>
#include <cuda_bf16.h>
#include <math.h>
#include <stdint.h>

#define BATCH   4
#define SEQ     2048
#define DIM     768
#define HEADS   12
#define HEAD_D  64
#define ATT_SCALE 0.125f   // 1/sqrt(64)
#define RS      (3 * DIM)

// ---------------- scratch (static device globals; no allocation) ----------------
__device__ float g_qkv[(size_t)BATCH * SEQ * 3 * DIM];             // [B,N,3C]
__device__ float g_att[(size_t)BATCH * SEQ * DIM];                 // [B,N,C]
__device__ float g_z  [(size_t)BATCH * HEADS * SEQ];               // Z1 per row
__device__ __nv_bfloat16 g_p[(size_t)BATCH * HEADS * SEQ * SEQ];   // e = exp(s), bf16

// ================================ helpers =======================================
static __device__ __forceinline__ uint32_t f2tf(float f) {
    uint32_t u;
    asm("cvt.rna.tf32.f32 %0, %1;" : "=r"(u) : "f"(f));
    return u;
}

// pack (lo, hi) floats -> bf16x2
static __device__ __forceinline__ uint32_t bf2(float lo, float hi) {
    uint32_t r;
    asm("cvt.rn.bf16x2.f32 %0, %1, %2;" : "=r"(r) : "f"(hi), "f"(lo));
    return r;
}

static __device__ __forceinline__ void mma8(float* c, const uint32_t* a, const uint32_t* b) {
    asm volatile(
        "mma.sync.aligned.m16n8k8.row.col.f32.tf32.tf32.f32 "
        "{%0,%1,%2,%3},{%4,%5,%6,%7},{%8,%9},{%0,%1,%2,%3};"
        : "+f"(c[0]), "+f"(c[1]), "+f"(c[2]), "+f"(c[3])
        : "r"(a[0]), "r"(a[1]), "r"(a[2]), "r"(a[3]), "r"(b[0]), "r"(b[1]));
}

static __device__ __forceinline__ void mma16(float* c, const uint32_t* a, const uint32_t* b) {
    asm volatile(
        "mma.sync.aligned.m16n8k16.row.col.f32.bf16.bf16.f32 "
        "{%0,%1,%2,%3},{%4,%5,%6,%7},{%8,%9},{%0,%1,%2,%3};"
        : "+f"(c[0]), "+f"(c[1]), "+f"(c[2]), "+f"(c[3])
        : "r"(a[0]), "r"(a[1]), "r"(a[2]), "r"(a[3]), "r"(b[0]), "r"(b[1]));
}

// FFMA-only expf (no MUFU): exp(x) for |x| < ~80, rel err ~3e-6
static __device__ __forceinline__ float fexp(float x) {
    float yy = x * 1.4426950408889634f;
    float z  = yy + 12582912.f;
    int  n23 = __float_as_int(z) << 23;
    float f  = yy - (z - 12582912.f);
    float t  = f * 0.6931471805599453f;
    float p  = fmaf(t, fmaf(t, fmaf(t, fmaf(t, fmaf(t,
               0.0083333333f, 0.0416666667f), 0.1666666667f), 0.5f), 1.f), 1.f);
    return __int_as_float(__float_as_int(p) + n23);
}

// =================================================================================
// GEMM-NT (tf32 mma.sync, double-buffered smem): C[M,N] = A[M,K]*B[N,K]^T (+bias)
// BM=BN=128, BK=16; 256 thr = 8 warps (2x4); warp tile 64x32.
// =================================================================================
#define TPITCH 20   // 16 + 4 pad (words) -> conflict-free operand fetch (4r+kc)

__global__ void __launch_bounds__(256)
gemm_tc(const float* __restrict__ A, const float* __restrict__ B,
        const float* __restrict__ bias, float* __restrict__ C,
        int M, int N, int K)
{
    __shared__ uint32_t As[2][128 * TPITCH];
    __shared__ uint32_t Bs[2][128 * TPITCH];

    const int tid = threadIdx.x;
    const int gid = (tid & 31) >> 2, t4 = tid & 3;
    const int w = tid >> 5, wr = w >> 2, wc = w & 3;
    const int m0 = blockIdx.y * 128, n0 = blockIdx.x * 128;
    const int lr = tid >> 2, lc = (tid & 3) * 4;

    float acc[4][4][4];
#pragma unroll
    for (int i = 0; i < 4; i++)
#pragma unroll
        for (int j = 0; j < 4; j++)
#pragma unroll
            for (int u = 0; u < 4; u++) acc[i][j][u] = 0.f;

    float4 pa0 = *(const float4*)&A[(size_t)(m0 + lr) * K + lc];
    float4 pa1 = *(const float4*)&A[(size_t)(m0 + lr + 64) * K + lc];
    float4 pb0 = *(const float4*)&B[(size_t)(n0 + lr) * K + lc];
    float4 pb1 = *(const float4*)&B[(size_t)(n0 + lr + 64) * K + lc];
    {
        uint32_t* d0 = &As[0][lr * TPITCH + lc];
        d0[0] = f2tf(pa0.x); d0[1] = f2tf(pa0.y); d0[2] = f2tf(pa0.z); d0[3] = f2tf(pa0.w);
        uint32_t* d1 = &As[0][(lr + 64) * TPITCH + lc];
        d1[0] = f2tf(pa1.x); d1[1] = f2tf(pa1.y); d1[2] = f2tf(pa1.z); d1[3] = f2tf(pa1.w);
        uint32_t* d2 = &Bs[0][lr * TPITCH + lc];
        d2[0] = f2tf(pb0.x); d2[1] = f2tf(pb0.y); d2[2] = f2tf(pb0.z); d2[3] = f2tf(pb0.w);
        uint32_t* d3 = &Bs[0][(lr + 64) * TPITCH + lc];
        d3[0] = f2tf(pb1.x); d3[1] = f2tf(pb1.y); d3[2] = f2tf(pb1.z); d3[3] = f2tf(pb1.w);
    }
    __syncthreads();

    const int nIter = K / 16;
    for (int i = 0; i < nIter; i++) {
        const int cur = i & 1;
        if (i + 1 < nIter) {
            const int kn = (i + 1) * 16;
            pa0 = *(const float4*)&A[(size_t)(m0 + lr) * K + kn + lc];
            pa1 = *(const float4*)&A[(size_t)(m0 + lr + 64) * K + kn + lc];
            pb0 = *(const float4*)&B[(size_t)(n0 + lr) * K + kn + lc];
            pb1 = *(const float4*)&B[(size_t)(n0 + lr + 64) * K + kn + lc];
        }
#pragma unroll
        for (int kk = 0; kk < 2; kk++) {
            const int kc = kk * 8 + t4;
            uint32_t af[4][4], bfr[4][2];
#pragma unroll
            for (int mt = 0; mt < 4; mt++) {
                int r = wr * 64 + mt * 16 + gid;
                af[mt][0] = As[cur][r * TPITCH + kc];
                af[mt][1] = As[cur][(r + 8) * TPITCH + kc];
                af[mt][2] = As[cur][r * TPITCH + kc + 4];
                af[mt][3] = As[cur][(r + 8) * TPITCH + kc + 4];
            }
#pragma unroll
            for (int nt = 0; nt < 4; nt++) {
                int n = wc * 32 + nt * 8 + gid;
                bfr[nt][0] = Bs[cur][n * TPITCH + kc];
                bfr[nt][1] = Bs[cur][n * TPITCH + kc + 4];
            }
#pragma unroll
            for (int mt = 0; mt < 4; mt++)
#pragma unroll
                for (int nt = 0; nt < 4; nt++)
                    mma8(acc[mt][nt], af[mt], bfr[nt]);
        }
        if (i + 1 < nIter) {
            const int nxt = cur ^ 1;
            uint32_t* d0 = &As[nxt][lr * TPITCH + lc];
            d0[0] = f2tf(pa0.x); d0[1] = f2tf(pa0.y); d0[2] = f2tf(pa0.z); d0[3] = f2tf(pa0.w);
            uint32_t* d1 = &As[nxt][(lr + 64) * TPITCH + lc];
            d1[0] = f2tf(pa1.x); d1[1] = f2tf(pa1.y); d1[2] = f2tf(pa1.z); d1[3] = f2tf(pa1.w);
            uint32_t* d2 = &Bs[nxt][lr * TPITCH + lc];
            d2[0] = f2tf(pb0.x); d2[1] = f2tf(pb0.y); d2[2] = f2tf(pb0.z); d2[3] = f2tf(pb0.w);
            uint32_t* d3 = &Bs[nxt][(lr + 64) * TPITCH + lc];
            d3[0] = f2tf(pb1.x); d3[1] = f2tf(pb1.y); d3[2] = f2tf(pb1.z); d3[3] = f2tf(pb1.w);
        }
        __syncthreads();
    }

#pragma unroll
    for (int mt = 0; mt < 4; mt++) {
        int r = m0 + wr * 64 + mt * 16 + gid;
#pragma unroll
        for (int nt = 0; nt < 4; nt++) {
            int col = n0 + wc * 32 + nt * 8 + t4 * 2;
            float b0 = 0.f, b1 = 0.f;
            if (bias) { b0 = bias[col]; b1 = bias[col + 1]; }
            float2 v0 = make_float2(acc[mt][nt][0] + b0, acc[mt][nt][1] + b1);
            float2 v1 = make_float2(acc[mt][nt][2] + b0, acc[mt][nt][3] + b1);
            *(float2*)&C[(size_t)r * N + col]       = v0;
            *(float2*)&C[(size_t)(r + 8) * N + col] = v1;
        }
    }
}

// =================================================================================
// attn1: per (b,h,128 q-rows) CTA. S = Q K^T (bf16 mma), e = exp(s*scale) -> g_p
// (bf16), Z1 per row -> g_z. No max pass (s*scale ~ N(0,1), exp safe).
// 8 warps (2 row-groups x 4 col-groups); warp tile 64x32 over S[128x128] chunks.
// smem pitch 36 words (pairs) -> conflict-free operand fetch (4r+kc).
// =================================================================================
__global__ void __launch_bounds__(256)
attn1_kernel(const float* __restrict__ qkv, uint32_t* __restrict__ P32,
             float* __restrict__ Zout)
{
    __shared__ uint32_t Qs[128 * 36];
    __shared__ uint32_t Ks[128 * 36];
    __shared__ float    Zp[128 * 4];

    const int tid = threadIdx.x;
    const int gid = (tid & 31) >> 2, t4 = tid & 3;
    const int w = tid >> 5, wr = w >> 2, wc = w & 3;
    const int b = blockIdx.z, h = blockIdx.y, n0 = blockIdx.x * 128;
    const int bh = b * HEADS + h;

    const float* Qg = qkv + (size_t)b * SEQ * RS + h * HEAD_D;
    const float* Kg = Qg + DIM;
    uint32_t* Pb = P32 + (size_t)bh * SEQ * 1024;

    // Q tile 128x64 -> bf16 pairs
#pragma unroll
    for (int i = 0; i < 8; i++) {
        int f = tid + 256 * i;
        int r = f >> 4, c4 = (f & 15) * 4;
        float4 v = *(const float4*)&Qg[(size_t)(n0 + r) * RS + c4];
        *(uint2*)&Qs[r * 36 + (c4 >> 1)] = make_uint2(bf2(v.x, v.y), bf2(v.z, v.w));
    }

    float zacc[4][2];
#pragma unroll
    for (int mt = 0; mt < 4; mt++) { zacc[mt][0] = 0.f; zacc[mt][1] = 0.f; }

    for (int c = 0; c < 16; c++) {
        __syncthreads();
#pragma unroll
        for (int i = 0; i < 8; i++) {
            int f = tid + 256 * i;
            int r = f >> 4, c4 = (f & 15) * 4;
            float4 v = *(const float4*)&Kg[(size_t)(c * 128 + r) * RS + c4];
            *(uint2*)&Ks[r * 36 + (c4 >> 1)] = make_uint2(bf2(v.x, v.y), bf2(v.z, v.w));
        }
        __syncthreads();

        float acc[4][4][4];
#pragma unroll
        for (int mt = 0; mt < 4; mt++)
#pragma unroll
            for (int nt = 0; nt < 4; nt++)
#pragma unroll
                for (int u = 0; u < 4; u++) acc[mt][nt][u] = 0.f;

#pragma unroll
        for (int kk = 0; kk < 4; kk++) {
            uint32_t af[4][4], bfr[4][2];
#pragma unroll
            for (int mt = 0; mt < 4; mt++) {
                int r = wr * 64 + mt * 16 + gid;
                af[mt][0] = Qs[r * 36 + kk * 8 + t4];
                af[mt][1] = Qs[(r + 8) * 36 + kk * 8 + t4];
                af[mt][2] = Qs[r * 36 + kk * 8 + t4 + 4];
                af[mt][3] = Qs[(r + 8) * 36 + kk * 8 + t4 + 4];
            }
#pragma unroll
            for (int nt = 0; nt < 4; nt++) {
                int n = wc * 32 + nt * 8 + gid;
                bfr[nt][0] = Ks[n * 36 + kk * 8 + t4];
                bfr[nt][1] = Ks[n * 36 + kk * 8 + t4 + 4];
            }
#pragma unroll
            for (int mt = 0; mt < 4; mt++)
#pragma unroll
                for (int nt = 0; nt < 4; nt++)
                    mma16(acc[mt][nt], af[mt], bfr[nt]);
        }

        // e = exp(s) -> bf16 gmem, Z1 partials
#pragma unroll
        for (int mt = 0; mt < 4; mt++) {
            int r0 = n0 + wr * 64 + mt * 16 + gid;
#pragma unroll
            for (int nt = 0; nt < 4; nt++) {
                int colp = c * 64 + wc * 16 + nt * 4 + t4;
                float e0 = fexp(acc[mt][nt][0] * ATT_SCALE);
                float e1 = fexp(acc[mt][nt][1] * ATT_SCALE);
                float e2 = fexp(acc[mt][nt][2] * ATT_SCALE);
                float e3 = fexp(acc[mt][nt][3] * ATT_SCALE);
                zacc[mt][0] += e0 + e1;
                zacc[mt][1] += e2 + e3;
                Pb[(size_t)r0 * 1024 + colp]       = bf2(e0, e1);
                Pb[(size_t)(r0 + 8) * 1024 + colp] = bf2(e2, e3);
            }
        }
    }

    // Z1 reduce: quad (t4) shuffle, stage per warp-column, final 4-sum (deterministic)
#pragma unroll
    for (int mt = 0; mt < 4; mt++)
#pragma unroll
        for (int hh = 0; hh < 2; hh++) {
            float z = zacc[mt][hh];
            z += __shfl_xor_sync(~0u, z, 1);
            z += __shfl_xor_sync(~0u, z, 2);
            zacc[mt][hh] = z;
        }
    if (t4 == 0) {
#pragma unroll
        for (int mt = 0; mt < 4; mt++)
#pragma unroll
            for (int hh = 0; hh < 2; hh++) {
                int rl = wr * 64 + mt * 16 + gid + 8 * hh;
                Zp[rl * 4 + wc] = zacc[mt][hh];
            }
    }
    __syncthreads();
    if (tid < 128) {
        float z = (Zp[tid * 4] + Zp[tid * 4 + 1]) + (Zp[tid * 4 + 2] + Zp[tid * 4 + 3]);
        Zout[(size_t)bh * SEQ + n0 + tid] = z;
    }
}

// =================================================================================
// attn2: per (b,h,128 q-rows) CTA.  pp = p + p^2/2 + p^3/6  (p = e/Z1), all bf16.
// O = (Sv + PP*V) / Z2,  Z2 = 2048 + sum(pp),  Sv = column sums of V (fp32 exact).
// 8 warps (4 row-groups x 2 col-groups); warp tile 32x32 over O[128x64].
// =================================================================================
#define A2_SMEM ((128 * 68 + 64 * 68) * 4 + (16 * 64 + 128 + 128 + 64) * 4)

__global__ void __launch_bounds__(256)
attn2_kernel(const float* __restrict__ qkv, const uint32_t* __restrict__ P32,
             const float* __restrict__ Zin, float* __restrict__ att)
{
    extern __shared__ uint32_t sm2[];
    uint32_t* Ps  = sm2;                        // [128][68] pp pairs
    uint32_t* Vt  = sm2 + 128 * 68;             // [64 d][68] V pairs (m-pairs)
    float*    SvP = (float*)(sm2 + 128 * 68 + 64 * 68);   // [16][64]
    float*    Zb  = SvP + 16 * 64;              // [128] Z2
    float*    sZ1 = Zb + 128;                   // [128] 1/Z1
    float*    Sv  = sZ1 + 128;                  // [64]

    const int tid = threadIdx.x;
    const int gid = (tid & 31) >> 2, t4 = tid & 3;
    const int w = tid >> 5, wq = w >> 1, wd = w & 1;
    const int b = blockIdx.z, h = blockIdx.y, n0 = blockIdx.x * 128;
    const int bh = b * HEADS + h;

    const float* Vg = qkv + (size_t)b * SEQ * RS + h * HEAD_D + 2 * DIM;
    const uint32_t* Pg = P32 + (size_t)bh * SEQ * 1024 + (size_t)n0 * 1024;

    if (tid < 128) sZ1[tid] = 1.0f / Zin[(size_t)bh * SEQ + n0 + tid];

    float acc[2][4][4];
#pragma unroll
    for (int i = 0; i < 2; i++)
#pragma unroll
        for (int j = 0; j < 4; j++)
#pragma unroll
            for (int u = 0; u < 4; u++) acc[i][j][u] = 0.f;
    float zacc = 0.f;
    float svacc[4] = {0.f, 0.f, 0.f, 0.f};

    const int d4 = (tid & 15) * 4;       // V-fill column group
    const int rr = tid >> 1, sub = tid & 1;  // pp-fill row / half

    __syncthreads();
    const float inv1 = sZ1[rr];

    for (int c = 0; c < 16; c++) {
        __syncthreads();
        // V chunk -> bf16 pairs (transposed) + fp32 column-sum accumulation
#pragma unroll
        for (int it = 0; it < 4; it++) {
            int mp = (tid >> 4) + 16 * it;
            const float* vp = &Vg[(size_t)(c * 128 + 2 * mp) * RS + d4];
            float4 a = *(const float4*)vp;
            float4 bb = *(const float4*)(vp + RS);
            svacc[0] += a.x + bb.x;
            svacc[1] += a.y + bb.y;
            svacc[2] += a.z + bb.z;
            svacc[3] += a.w + bb.w;
            Vt[(d4 + 0) * 68 + mp] = bf2(a.x, bb.x);
            Vt[(d4 + 1) * 68 + mp] = bf2(a.y, bb.y);
            Vt[(d4 + 2) * 68 + mp] = bf2(a.z, bb.z);
            Vt[(d4 + 3) * 68 + mp] = bf2(a.w, bb.w);
        }
        // e -> pp = p + p^2/2 + p^3/6, accumulate Z2, store bf16 pairs
#pragma unroll
        for (int it = 0; it < 8; it++) {
            int c16 = sub * 8 + it;
            uint4 ev = *(const uint4*)&Pg[(size_t)rr * 1024 + c * 64 + c16 * 4];
            uint32_t ws[4] = {ev.x, ev.y, ev.z, ev.w};
            uint32_t* d = &Ps[rr * 68 + c16 * 4];
#pragma unroll
            for (int u = 0; u < 4; u++) {
                float p0 = __uint_as_float(ws[u] << 16) * inv1;
                float p1 = __uint_as_float(ws[u] & 0xffff0000u) * inv1;
                float t0 = fmaf(p0, 0.16666667f, 0.5f);
                float t1 = fmaf(p1, 0.16666667f, 0.5f);
                float pp0 = p0 * fmaf(p0, t0, 1.0f);
                float pp1 = p1 * fmaf(p1, t1, 1.0f);
                zacc += pp0 + pp1;
                d[u] = bf2(pp0, pp1);
            }
        }
        __syncthreads();
        // D += PP * V
#pragma unroll
        for (int kk = 0; kk < 8; kk++) {
            uint32_t af[2][4], bfr[4][2];
#pragma unroll
            for (int mt = 0; mt < 2; mt++) {
                int r = wq * 32 + mt * 16 + gid;
                af[mt][0] = Ps[r * 68 + kk * 8 + t4];
                af[mt][1] = Ps[(r + 8) * 68 + kk * 8 + t4];
                af[mt][2] = Ps[r * 68 + kk * 8 + t4 + 4];
                af[mt][3] = Ps[(r + 8) * 68 + kk * 8 + t4 + 4];
            }
#pragma unroll
            for (int nt = 0; nt < 4; nt++) {
                int n = wd * 32 + nt * 8 + gid;
                bfr[nt][0] = Vt[n * 68 + kk * 8 + t4];
                bfr[nt][1] = Vt[n * 68 + kk * 8 + t4 + 4];
            }
#pragma unroll
            for (int mt = 0; mt < 2; mt++)
#pragma unroll
                for (int nt = 0; nt < 4; nt++)
                    mma16(acc[mt][nt], af[mt], bfr[nt]);
        }
    }

    // Z2 per row (pairs of threads share row rr)
    {
        float z = zacc + __shfl_xor_sync(~0u, zacc, 1);
        if (sub == 0) Zb[rr] = 2048.f + z;
    }
    // Sv reduce (deterministic fixed order)
#pragma unroll
    for (int u = 0; u < 4; u++) SvP[(tid >> 4) * 64 + d4 + u] = svacc[u];
    __syncthreads();
    if (tid < 64) {
        float s = 0.f;
#pragma unroll
        for (int g = 0; g < 16; g++) s += SvP[g * 64 + tid];
        Sv[tid] = s;
    }
    __syncthreads();

    // epilogue: O = (Sv + D) / Z2
#pragma unroll
    for (int mt = 0; mt < 2; mt++) {
        int r0 = wq * 32 + mt * 16 + gid;
        float i0 = 1.0f / Zb[r0];
        float i1 = 1.0f / Zb[r0 + 8];
#pragma unroll
        for (int nt = 0; nt < 4; nt++) {
            int cd = wd * 32 + nt * 8 + 2 * t4;
            float s0 = Sv[cd], s1 = Sv[cd + 1];
            float2 v0 = make_float2((acc[mt][nt][0] + s0) * i0, (acc[mt][nt][1] + s1) * i0);
            float2 v1 = make_float2((acc[mt][nt][2] + s0) * i1, (acc[mt][nt][3] + s1) * i1);
            *(float2*)&att[(size_t)(b * SEQ + n0 + r0) * DIM + h * HEAD_D + cd]     = v0;
            *(float2*)&att[(size_t)(b * SEQ + n0 + r0 + 8) * DIM + h * HEAD_D + cd] = v1;
        }
    }
}

// =================================================================================
// launch
// =================================================================================
extern "C" void kernel_launch(void* const* d_in, const int* in_sizes, int n_in,
                              void* d_out, int out_size)
{
    const float* x      = (const float*)d_in[0];   // [4,2048,768]
    const float* w_qkv  = (const float*)d_in[1];   // [2304,768]
    const float* w_proj = (const float*)d_in[2];   // [768,768]
    const float* b_proj = (const float*)d_in[3];   // [768]
    float* out = (float*)d_out;                    // [4,2048,768]

    void* p0; cudaGetSymbolAddress(&p0, g_qkv);
    void* p1; cudaGetSymbolAddress(&p1, g_att);
    void* p2; cudaGetSymbolAddress(&p2, g_z);
    void* p3; cudaGetSymbolAddress(&p3, g_p);
    float* qkv = (float*)p0;
    float* att = (float*)p1;
    float* zbuf = (float*)p2;
    uint32_t* pbuf = (uint32_t*)p3;

    cudaFuncSetAttribute(attn2_kernel, cudaFuncAttributeMaxDynamicSharedMemorySize, A2_SMEM);

    const int M = BATCH * SEQ;   // 8192

    // 1) qkv = x @ w_qkv^T
    {
        dim3 grid((3 * DIM) / 128, M / 128);
        gemm_tc<<<grid, 256>>>(x, w_qkv, nullptr, qkv, M, 3 * DIM, DIM);
    }
    // 2a) S=QK^T (bf16), e=exp(s), Z1
    {
        dim3 grid(SEQ / 128, HEADS, BATCH);
        attn1_kernel<<<grid, 256>>>(qkv, pbuf, zbuf);
    }
    // 2b) pp=p+p^2/2+p^3/6, O=(Sv + PP V)/Z2
    {
        dim3 grid(SEQ / 128, HEADS, BATCH);
        attn2_kernel<<<grid, 256, A2_SMEM>>>(qkv, pbuf, zbuf, att);
    }
    // 3) out = att @ w_proj^T + b
    {
        dim3 grid(DIM / 128, M / 128);
        gemm_tc<<<grid, 256>>>(att, w_proj, b_proj, out, M, DIM, DIM);
    }
}